// round 7
// baseline (speedup 1.0000x reference)
#include <cuda_runtime.h>
#include <math.h>

#define NPTS   65536
#define NN     34
#define KP     15
#define INF    64
#define OUTF   64
#define OFFD   60
#define EXTENTF 0.5f
#define PPB    16
#define TPB    1024
#define NBLK   (NPTS / PPB)      // 4096
#define NI     (KP * INF)        // 960
#define NI4    (NI / 4)          // 240
#define SLOT_I4 (NI4 / PPB)      // 15 i4-blocks per slot

// ---------------- device scratch (no allocations allowed) ----------------
__device__ __align__(16) float g_owT[NI4 * 64 * 4];   // blocked transpose of offset_weight (cols 60..63 = 0)
__device__ __align__(16) float g_wT [NI4 * 64 * 4];   // blocked transpose of weight
__device__ float g_psum  [NBLK * OUTF];
__device__ float g_psumsq[NBLK * OUTF];
__device__ __align__(16) float g_scale[OUTF];
__device__ __align__(16) float g_shift[OUTF];

// packed fp32x2 FMA: acc = a*b + acc (Blackwell FFMA2)
__device__ __forceinline__ void f2fma(float2 &acc, float2 a, float2 b) {
    asm("{\n\t"
        ".reg .b64 ra, rb, rc;\n\t"
        "mov.b64 ra, {%2, %3};\n\t"
        "mov.b64 rb, {%4, %5};\n\t"
        "mov.b64 rc, {%0, %1};\n\t"
        "fma.rn.f32x2 rc, ra, rb, rc;\n\t"
        "mov.b64 {%0, %1}, rc;\n\t"
        "}"
        : "+f"(acc.x), "+f"(acc.y)
        : "f"(a.x), "f"(a.y), "f"(b.x), "f"(b.y));
}

// ---------------- prep: blocked transposes of the two weight matrices ----------------
__global__ void prep_kernel(const float* __restrict__ ow, const float* __restrict__ w) {
    int t = blockIdx.x * blockDim.x + threadIdx.x;
    int stride = gridDim.x * blockDim.x;
    // offset_weight: [K,IN,60] linear (i*60+d), i = k*64+c
    for (int idx = t; idx < NI * OFFD; idx += stride) {
        int i = idx / OFFD, d = idx - i * OFFD;
        g_owT[((i >> 2) * 64 + d) * 4 + (i & 3)] = ow[idx];
    }
    // weight: [K,IN,64] linear (i*64+o)
    for (int idx = t; idx < NI * OUTF; idx += stride) {
        int i = idx / OUTF, o = idx - i * OUTF;
        g_wT[((i >> 2) * 64 + o) * 4 + (i & 3)] = w[idx];
    }
}

// ---------------- main fused kernel: 16 points per CTA, 1024 threads ----------------
// Shared memory carve (floats):
//   s_u   [16*1024]           wf buffer (stride 1024/pt) ALIASED with s_red[pp][slot][64]
//   s_w   [16][34][20]        influence weights (15 used + pad)
//   s_pts [16][34][4]         neighbor offsets
//   s_f0  [16][64]            f0 / reused as x for BN partials
//   s_dkp [16][15][4]         deformed kp xyz + modulation
//   s_idx [16][34] (int)
__global__ __launch_bounds__(TPB, 1) void kpconv_kernel(
    const float* __restrict__ query,
    const float* __restrict__ support,
    const int*   __restrict__ nbr,
    const float* __restrict__ feat,
    const float* __restrict__ obias,
    const float* __restrict__ kpts,
    float*       __restrict__ out)
{
    extern __shared__ __align__(16) float sm[];
    float* s_u   = sm;                       // 16384 floats
    float* s_w   = sm + 16384;               // 10880
    float* s_pts = s_w + 10880;              // 2176
    float* s_f0  = s_pts + 2176;             // 1024
    float* s_dkp = s_f0 + 1024;              // 960
    int*   s_idx = (int*)(s_dkp + 960);      // 544

    const int tid = threadIdx.x;
    const int p   = tid >> 6;      // point slot 0..15
    const int t   = tid & 63;      // channel / lane role
    const int n   = blockIdx.x * PPB + p;

    // ===== Phase A: neighbor geometry + rigid influence weights =====
    if (t < NN) {
        float qx = query[n*3+0], qy = query[n*3+1], qz = query[n*3+2];
        int id = nbr[n*NN + t];
        s_idx[p*NN + t] = id;
        float px = support[id*3+0] - qx;
        float py = support[id*3+1] - qy;
        float pz = support[id*3+2] - qz;
        float* pr = &s_pts[(p*NN + t)*4];
        pr[0] = px; pr[1] = py; pr[2] = pz;
        float wl[16];
        #pragma unroll
        for (int k = 0; k < KP; k++) {
            float dx = px - kpts[k*3+0];
            float dy = py - kpts[k*3+1];
            float dz = pz - kpts[k*3+2];
            float sq = dx*dx + dy*dy + dz*dz;
            wl[k] = fmaxf(1.0f - 2.0f * sqrtf(sq), 0.0f);
        }
        wl[15] = 0.0f;
        float* wr = &s_w[(p*NN + t)*20];
        #pragma unroll
        for (int j = 0; j < 4; j++)
            *(float4*)&wr[j*4] = make_float4(wl[j*4+0], wl[j*4+1], wl[j*4+2], wl[j*4+3]);
    }
    __syncthreads();

    // ===== Phase B: wf0[k] = sum_a w0[a,k] * feat[a, c=t] =====
    {
        float2 wf[8];
        #pragma unroll
        for (int k = 0; k < 8; k++) wf[k] = make_float2(0.f, 0.f);
        const int ib = p * NN;
        #pragma unroll 2
        for (int a = 0; a < NN; a++) {
            float f = feat[s_idx[ib + a] * INF + t];
            float2 ff = make_float2(f, f);
            const float4* wr = (const float4*)&s_w[(ib + a)*20];
            float4 w0 = wr[0], w1 = wr[1], w2 = wr[2], w3 = wr[3];
            f2fma(wf[0], make_float2(w0.x, w0.y), ff);
            f2fma(wf[1], make_float2(w0.z, w0.w), ff);
            f2fma(wf[2], make_float2(w1.x, w1.y), ff);
            f2fma(wf[3], make_float2(w1.z, w1.w), ff);
            f2fma(wf[4], make_float2(w2.x, w2.y), ff);
            f2fma(wf[5], make_float2(w2.z, w2.w), ff);
            f2fma(wf[6], make_float2(w3.x, w3.y), ff);
            f2fma(wf[7], make_float2(w3.z, w3.w), ff);
        }
        #pragma unroll
        for (int k = 0; k < KP; k++) {
            float v = (k & 1) ? wf[k >> 1].y : wf[k >> 1].x;
            s_u[p*1024 + k*INF + t] = v;
        }
    }
    __syncthreads();

    // ===== Phase C: f0[d] = bias[d] + sum_i wf0[i]*ow[i,d]; slot p covers 15 i4-blocks for ALL 16 points =====
    {
        float2 acc[PPB];
        #pragma unroll
        for (int pp = 0; pp < PPB; pp++) acc[pp] = make_float2(0.f, 0.f);
        const int pbase = p * SLOT_I4;
        #pragma unroll 3
        for (int it = 0; it < SLOT_I4; it++) {
            int i4 = pbase + it;
            float4 w4 = *(const float4*)&g_owT[(i4 * 64 + t) * 4];
            #pragma unroll
            for (int pp = 0; pp < PPB; pp++) {
                float4 v4 = *(const float4*)&s_u[pp*1024 + i4*4];
                f2fma(acc[pp], make_float2(v4.x, v4.y), make_float2(w4.x, w4.y));
                f2fma(acc[pp], make_float2(v4.z, v4.w), make_float2(w4.z, w4.w));
            }
        }
        __syncthreads();   // all slots finished reading s_u (wf) -> safe to alias as s_red
        #pragma unroll
        for (int pp = 0; pp < PPB; pp++)
            s_u[pp*1024 + p*64 + t] = acc[pp].x + acc[pp].y;   // s_red[pp][p][t]
    }
    __syncthreads();
    if (t < OFFD) {
        float f0 = obias[t];
        #pragma unroll
        for (int s = 0; s < PPB; s++) f0 += s_u[p*1024 + s*64 + t];
        s_f0[p*64 + t] = f0;
    }
    __syncthreads();

    // ===== offsets + modulations -> deformed kernel points =====
    if (t < KP) {
        float ox = s_f0[p*64 + 3*t+0] * EXTENTF;
        float oy = s_f0[p*64 + 3*t+1] * EXTENTF;
        float oz = s_f0[p*64 + 3*t+2] * EXTENTF;
        float* dk = &s_dkp[(p*KP + t)*4];
        dk[0] = kpts[t*3+0] + ox;
        dk[1] = kpts[t*3+1] + oy;
        dk[2] = kpts[t*3+2] + oz;
        dk[3] = 2.0f / (1.0f + expf(-s_f0[p*64 + 45 + t]));   // modulation
    }
    __syncthreads();

    // ===== Phase A2: deformed influence weights =====
    if (t < NN) {
        const float* pr = &s_pts[(p*NN + t)*4];
        float px = pr[0], py = pr[1], pz = pr[2];
        float wl[16];
        #pragma unroll
        for (int k = 0; k < KP; k++) {
            const float* dk = &s_dkp[(p*KP + k)*4];
            float dx = px - dk[0];
            float dy = py - dk[1];
            float dz = pz - dk[2];
            float sq = dx*dx + dy*dy + dz*dz;
            wl[k] = fmaxf(1.0f - 2.0f * sqrtf(sq), 0.0f);
        }
        wl[15] = 0.0f;
        float* wr = &s_w[(p*NN + t)*20];
        #pragma unroll
        for (int j = 0; j < 4; j++)
            *(float4*)&wr[j*4] = make_float4(wl[j*4+0], wl[j*4+1], wl[j*4+2], wl[j*4+3]);
    }
    __syncthreads();

    // ===== Phase D: wf[k] = mod[k] * sum_a w[a,k] * feat[a, c=t] =====
    {
        float2 wf[8];
        #pragma unroll
        for (int k = 0; k < 8; k++) wf[k] = make_float2(0.f, 0.f);
        const int ib = p * NN;
        #pragma unroll 2
        for (int a = 0; a < NN; a++) {
            float f = feat[s_idx[ib + a] * INF + t];
            float2 ff = make_float2(f, f);
            const float4* wr = (const float4*)&s_w[(ib + a)*20];
            float4 w0 = wr[0], w1 = wr[1], w2 = wr[2], w3 = wr[3];
            f2fma(wf[0], make_float2(w0.x, w0.y), ff);
            f2fma(wf[1], make_float2(w0.z, w0.w), ff);
            f2fma(wf[2], make_float2(w1.x, w1.y), ff);
            f2fma(wf[3], make_float2(w1.z, w1.w), ff);
            f2fma(wf[4], make_float2(w2.x, w2.y), ff);
            f2fma(wf[5], make_float2(w2.z, w2.w), ff);
            f2fma(wf[6], make_float2(w3.x, w3.y), ff);
            f2fma(wf[7], make_float2(w3.z, w3.w), ff);
        }
        #pragma unroll
        for (int k = 0; k < KP; k++) {
            float v = (k & 1) ? wf[k >> 1].y : wf[k >> 1].x;
            s_u[p*1024 + k*INF + t] = v * s_dkp[(p*KP + k)*4 + 3];
        }
    }
    __syncthreads();

    // ===== Phase E: x[o] = sum_i wf[i] * weight[i,o] =====
    {
        float2 acc[PPB];
        #pragma unroll
        for (int pp = 0; pp < PPB; pp++) acc[pp] = make_float2(0.f, 0.f);
        const int pbase = p * SLOT_I4;
        #pragma unroll 3
        for (int it = 0; it < SLOT_I4; it++) {
            int i4 = pbase + it;
            float4 w4 = *(const float4*)&g_wT[(i4 * 64 + t) * 4];
            #pragma unroll
            for (int pp = 0; pp < PPB; pp++) {
                float4 v4 = *(const float4*)&s_u[pp*1024 + i4*4];
                f2fma(acc[pp], make_float2(v4.x, v4.y), make_float2(w4.x, w4.y));
                f2fma(acc[pp], make_float2(v4.z, v4.w), make_float2(w4.z, w4.w));
            }
        }
        __syncthreads();
        #pragma unroll
        for (int pp = 0; pp < PPB; pp++)
            s_u[pp*1024 + p*64 + t] = acc[pp].x + acc[pp].y;
    }
    __syncthreads();
    {
        float x = 0.f;
        #pragma unroll
        for (int s = 0; s < PPB; s++) x += s_u[p*1024 + s*64 + t];
        out[n * OUTF + t] = x;
        s_f0[p*64 + t] = x;                 // reuse as x buffer for BN partials
    }
    __syncthreads();
    if (tid < OUTF) {
        float s = 0.f, s2 = 0.f;
        #pragma unroll
        for (int pp = 0; pp < PPB; pp++) {
            float v = s_f0[pp*64 + tid];
            s += v; s2 += v * v;
        }
        g_psum  [blockIdx.x * OUTF + tid] = s;
        g_psumsq[blockIdx.x * OUTF + tid] = s2;
    }
}

// ---------------- BN stats: one block per channel (deterministic fixed-order reduce) ----------------
__global__ void stats_kernel(const float* __restrict__ gamma, const float* __restrict__ beta) {
    int o = blockIdx.x;
    int tid = threadIdx.x;
    float s = 0.f, s2 = 0.f;
    for (int j = tid; j < NBLK; j += blockDim.x) {
        s  += g_psum  [j * OUTF + o];
        s2 += g_psumsq[j * OUTF + o];
    }
    __shared__ float sh[256], sh2[256];
    sh[tid] = s; sh2[tid] = s2;
    __syncthreads();
    for (int st = 128; st > 0; st >>= 1) {
        if (tid < st) { sh[tid] += sh[tid + st]; sh2[tid] += sh2[tid + st]; }
        __syncthreads();
    }
    if (tid == 0) {
        float mean = sh[0]  / (float)NPTS;
        float var  = sh2[0] / (float)NPTS - mean * mean;
        float sc   = rsqrtf(var + 1e-6f) * gamma[o];
        g_scale[o] = sc;
        g_shift[o] = beta[o] - mean * sc;
    }
}

// ---------------- BN apply + LeakyReLU ----------------
__global__ void bn_kernel(float* __restrict__ out) {
    const int total4 = NPTS * OUTF / 4;
    for (int i = blockIdx.x * blockDim.x + threadIdx.x; i < total4; i += gridDim.x * blockDim.x) {
        float4 v = ((float4*)out)[i];
        int ch = (i & 15) * 4;
        float4 sc = *(const float4*)&g_scale[ch];
        float4 sh = *(const float4*)&g_shift[ch];
        v.x = v.x * sc.x + sh.x;  v.x = v.x >= 0.f ? v.x : 0.1f * v.x;
        v.y = v.y * sc.y + sh.y;  v.y = v.y >= 0.f ? v.y : 0.1f * v.y;
        v.z = v.z * sc.z + sh.z;  v.z = v.z >= 0.f ? v.z : 0.1f * v.z;
        v.w = v.w * sc.w + sh.w;  v.w = v.w >= 0.f ? v.w : 0.1f * v.w;
        ((float4*)out)[i] = v;
    }
}

// ---------------- launch ----------------
extern "C" void kernel_launch(void* const* d_in, const int* in_sizes, int n_in,
                              void* d_out, int out_size) {
    const float* query   = (const float*)d_in[0];
    const float* support = (const float*)d_in[1];
    const int*   nbr     = (const int*)  d_in[2];
    const float* feat    = (const float*)d_in[3];
    const float* weight  = (const float*)d_in[4];
    const float* ow      = (const float*)d_in[5];
    const float* obias   = (const float*)d_in[6];
    const float* gamma   = (const float*)d_in[7];
    const float* beta    = (const float*)d_in[8];
    const float* kpts    = (const float*)d_in[9];
    float* out = (float*)d_out;

    const int smem_bytes = (16384 + 10880 + 2176 + 1024 + 960 + 544) * 4;  // 127,872 B
    static int attr_set = 0;
    if (!attr_set) {
        cudaFuncSetAttribute(kpconv_kernel, cudaFuncAttributeMaxDynamicSharedMemorySize, smem_bytes);
        attr_set = 1;
    }

    prep_kernel<<<120, 512>>>(ow, weight);
    kpconv_kernel<<<NBLK, TPB, smem_bytes>>>(query, support, nbr, feat, obias, kpts, out);
    stats_kernel<<<OUTF, 256>>>(gamma, beta);
    bn_kernel<<<2048, 256>>>(out);
}